// round 15
// baseline (speedup 1.0000x reference)
#include <cuda_runtime.h>
#include <cstdint>

#define N_NODES 50000
#define N_EDGES 1600000
#define IN_DIM 64
#define HD 64
#define NUM_HEADS 4
#define OUT_DIM 16

// ---------------- device scratch ----------------
__device__ float g_Q[N_NODES * HD];
__device__ float g_K[N_NODES * HD];
__device__ float g_V[N_NODES * HD];
__device__ float g_Z[N_NODES * NUM_HEADS];

// ---------------- helpers ----------------
__device__ __forceinline__ void red_add_v4(float* p, float a, float b, float c, float d) {
    asm volatile("red.global.add.v4.f32 [%0], {%1,%2,%3,%4};"
                 :: "l"(p), "f"(a), "f"(b), "f"(c), "f"(d) : "memory");
}
__device__ __forceinline__ uint32_t f2tf32(float f) {
    uint32_t r;
    asm("cvt.rna.tf32.f32 %0, %1;" : "=r"(r) : "f"(f));
    return r;
}
__device__ __forceinline__ void mma_tf32(float d[4], uint32_t a0, uint32_t a1,
                                         uint32_t a2, uint32_t a3,
                                         uint32_t b0, uint32_t b1) {
    asm("mma.sync.aligned.m16n8k8.row.col.f32.tf32.tf32.f32 "
        "{%0,%1,%2,%3}, {%4,%5,%6,%7}, {%8,%9}, {%0,%1,%2,%3};"
        : "+f"(d[0]), "+f"(d[1]), "+f"(d[2]), "+f"(d[3])
        : "r"(a0), "r"(a1), "r"(a2), "r"(a3), "r"(b0), "r"(b1));
}
__device__ __forceinline__ uint32_t smem_u32(const void* p) {
    uint32_t a;
    asm("{ .reg .u64 t; cvta.to.shared.u64 t, %1; cvt.u32.u64 %0, t; }" : "=r"(a) : "l"(p));
    return a;
}
__device__ __forceinline__ void cp_async16(uint32_t saddr, const void* gptr) {
    asm volatile("cp.async.cg.shared.global [%0], [%1], 16;" :: "r"(saddr), "l"(gptr));
}

// ---------------- zero init ----------------
__global__ void zero_kernel(float* __restrict__ out) {
    int i = blockIdx.x * blockDim.x + threadIdx.x;
    if (i < N_NODES * HD) out[i] = 0.0f;
    if (i < N_NODES * NUM_HEADS) g_Z[i] = 0.0f;
}

// ---------------- node projections (R3 scalar, known good) ----------------
#define PROJ_SMEM_FLOATS (128 * 65 + 64 * 64 + 64)
__global__ __launch_bounds__(128)
void proj_kernel(const float* __restrict__ x,
                 const float* __restrict__ WQ, const float* __restrict__ bQ,
                 const float* __restrict__ WK, const float* __restrict__ bK,
                 const float* __restrict__ WV, const float* __restrict__ bV) {
    const float* W; const float* b; float* out;
    if (blockIdx.y == 0)      { W = WQ; b = bQ; out = g_Q; }
    else if (blockIdx.y == 1) { W = WK; b = bK; out = g_K; }
    else                      { W = WV; b = bV; out = g_V; }

    extern __shared__ float sm[];
    float* x_s = sm;
    float* w_s = sm + 128 * 65;
    float* b_s = w_s + 64 * 64;

    const int tid = threadIdx.x;
    const int base = blockIdx.x * 128;

    {
        const float4* W4 = reinterpret_cast<const float4*>(W);
        float4* ws4 = reinterpret_cast<float4*>(w_s);
        #pragma unroll
        for (int i = tid; i < 1024; i += 128) ws4[i] = W4[i];
    }
    if (tid < 64) b_s[tid] = b[tid];

    for (int f = tid; f < 128 * 16; f += 128) {
        int r = f >> 4, q = f & 15;
        int gr = base + r;
        if (gr >= N_NODES) gr = N_NODES - 1;
        float4 v = reinterpret_cast<const float4*>(x + (size_t)gr * 64)[q];
        float* d = x_s + r * 65 + q * 4;
        d[0] = v.x; d[1] = v.y; d[2] = v.z; d[3] = v.w;
    }
    __syncthreads();

    const int eg = tid >> 3, dg = tid & 7;

    float acc[8][8];
    #pragma unroll
    for (int i = 0; i < 8; i++)
        #pragma unroll
        for (int j = 0; j < 8; j++) acc[i][j] = 0.0f;

    const float4* ws4 = reinterpret_cast<const float4*>(w_s);
    #pragma unroll 4
    for (int c = 0; c < 64; c++) {
        float4 w0 = ws4[c * 16 + dg * 2];
        float4 w1 = ws4[c * 16 + dg * 2 + 1];
        float a[8];
        #pragma unroll
        for (int i = 0; i < 8; i++) a[i] = x_s[(eg * 8 + i) * 65 + c];
        #pragma unroll
        for (int i = 0; i < 8; i++) {
            acc[i][0] += a[i] * w0.x; acc[i][1] += a[i] * w0.y;
            acc[i][2] += a[i] * w0.z; acc[i][3] += a[i] * w0.w;
            acc[i][4] += a[i] * w1.x; acc[i][5] += a[i] * w1.y;
            acc[i][6] += a[i] * w1.z; acc[i][7] += a[i] * w1.w;
        }
    }

    float bb[8];
    #pragma unroll
    for (int j = 0; j < 8; j++) bb[j] = b_s[dg * 8 + j];
    #pragma unroll
    for (int i = 0; i < 8; i++) {
        int n = base + eg * 8 + i;
        if (n < N_NODES) {
            float4 o0 = make_float4(acc[i][0] + bb[0], acc[i][1] + bb[1], acc[i][2] + bb[2], acc[i][3] + bb[3]);
            float4 o1 = make_float4(acc[i][4] + bb[4], acc[i][5] + bb[5], acc[i][6] + bb[6], acc[i][7] + bb[7]);
            float4* dst = reinterpret_cast<float4*>(out + (size_t)n * 64 + dg * 8);
            dst[0] = o0; dst[1] = o1;
        }
    }
}

// ---------------- fused edge kernel: cp.async gather prefetch + tf32 mma ----
// smem layout (floats):
#define TILE_E   64
#define EA_OFF   0                         // 64 x 68  (tf32 in, fp32 E out)
#define EA_STR   68
#define W_OFF    (TILE_E * 68)             // 64 x 72
#define W_STR    72
#define BIAS_OFF (W_OFF + 64 * 72)         // 64
#define SI_OFF   (BIAS_OFF + 64)           // 64 ints
#define DI_OFF   (SI_OFF + TILE_E)         // 64 ints
#define KQV_OFF  (DI_OFF + TILE_E)         // 64 x 196 (K:0..63, Q:64..127, V:128..191, pad 4)
#define KQV_STR  196
#define EDGE_SMEM_FLOATS (KQV_OFF + TILE_E * KQV_STR)

__global__ __launch_bounds__(128, 2)
void edge_kernel(const float* __restrict__ ea,
                 const int* __restrict__ eidx,
                 const float* __restrict__ WE, const float* __restrict__ bE,
                 float* __restrict__ out) {
    extern __shared__ float sm[];
    uint32_t* ea_s = reinterpret_cast<uint32_t*>(sm + EA_OFF);
    float* E_s     = sm + EA_OFF;               // reused after MMA
    uint32_t* w_s  = reinterpret_cast<uint32_t*>(sm + W_OFF);
    float* bias_s  = sm + BIAS_OFF;
    int* si_s      = reinterpret_cast<int*>(sm + SI_OFF);
    int* di_s      = reinterpret_cast<int*>(sm + DI_OFF);
    float* kqv_s   = sm + KQV_OFF;

    const int tid = threadIdx.x;
    const int base = blockIdx.x * TILE_E;

    if (tid < 64) bias_s[tid] = bE[tid];
    if (tid < TILE_E) {
        si_s[tid] = __ldcs(eidx + base + tid);
        di_s[tid] = __ldcs(eidx + N_EDGES + base + tid);
    }

    // stage A = ea tile (tf32 bits), stride 68 — streaming loads
    for (int f = tid; f < TILE_E * 16; f += 128) {
        int r = f >> 4, q = f & 15;
        float4 v = __ldcs(reinterpret_cast<const float4*>(ea + (size_t)(base + r) * 64) + q);
        uint4 t;
        t.x = f2tf32(v.x); t.y = f2tf32(v.y); t.z = f2tf32(v.z); t.w = f2tf32(v.w);
        *reinterpret_cast<uint4*>(ea_s + r * EA_STR + q * 4) = t;
    }
    // stage B = WE (row-major [k][n]) as tf32 bits, stride 72
    for (int f = tid; f < 64 * 16; f += 128) {
        int k = f >> 4, q = f & 15;
        float4 v = reinterpret_cast<const float4*>(WE + (size_t)k * 64)[q];
        uint4 t;
        t.x = f2tf32(v.x); t.y = f2tf32(v.y); t.z = f2tf32(v.z); t.w = f2tf32(v.w);
        *reinterpret_cast<uint4*>(w_s + k * W_STR + q * 4) = t;
    }
    __syncthreads();   // si/di + A/W tiles visible

    // ---- issue K/Q/V gather prefetch: 64 edges x 48 x 16B chunks = 3072 ----
    {
        const uint32_t kqv_base = smem_u32(kqv_s);
        for (int f = tid; f < TILE_E * 48; f += 128) {
            const int le = f / 48;
            const int c  = f - le * 48;      // 0..47
            const int kind = c >> 4;         // 0=K,1=Q,2=V
            const int q4   = c & 15;         // 16B chunk within the 64 floats
            const int node = (kind == 1) ? di_s[le] : si_s[le];
            const float* gp = (kind == 0 ? g_K : (kind == 1 ? g_Q : g_V))
                              + (size_t)node * 64 + q4 * 4;
            cp_async16(kqv_base + (uint32_t)(le * KQV_STR + kind * 64 + q4 * 4) * 4u, gp);
        }
        asm volatile("cp.async.commit_group;" ::: "memory");
    }

    const int lane = tid & 31;
    const int warp = tid >> 5;
    const int g  = lane >> 2;
    const int tg = lane & 3;
    const int wrow = warp * 16;

    // ---- Phase A: E = ea @ WE via m16n8k8 tf32 mma (overlaps the cp.async) ----
    float acc[8][4];
    #pragma unroll
    for (int nt = 0; nt < 8; nt++)
        #pragma unroll
        for (int j = 0; j < 4; j++) acc[nt][j] = 0.0f;

    #pragma unroll
    for (int k8 = 0; k8 < 8; k8++) {
        const int r0 = wrow + g;
        uint32_t a0 = ea_s[(r0)     * EA_STR + k8 * 8 + tg];
        uint32_t a1 = ea_s[(r0 + 8) * EA_STR + k8 * 8 + tg];
        uint32_t a2 = ea_s[(r0)     * EA_STR + k8 * 8 + tg + 4];
        uint32_t a3 = ea_s[(r0 + 8) * EA_STR + k8 * 8 + tg + 4];
        #pragma unroll
        for (int nt = 0; nt < 8; nt++) {
            uint32_t b0 = w_s[(k8 * 8 + tg)     * W_STR + nt * 8 + g];
            uint32_t b1 = w_s[(k8 * 8 + tg + 4) * W_STR + nt * 8 + g];
            mma_tf32(acc[nt], a0, a1, a2, a3, b0, b1);
        }
    }

    // ---- store E (+bias) into this warp's own rows ----
    #pragma unroll
    for (int rr = 0; rr < 2; rr++) {
        const int row = wrow + rr * 8 + g;
        #pragma unroll
        for (int nt = 0; nt < 8; nt++) {
            const int c0 = nt * 8 + tg * 2;
            float2 bb = *reinterpret_cast<const float2*>(bias_s + c0);
            *reinterpret_cast<float2*>(E_s + row * EA_STR + c0) =
                make_float2(acc[nt][rr * 2 + 0] + bb.x,
                            acc[nt][rr * 2 + 1] + bb.y);
        }
    }
    asm volatile("cp.async.wait_all;" ::: "memory");
    __syncthreads();   // E + gathered K/Q/V visible

    // ---- Phase B: per (edge, head): score from smem + scatter ----
    #pragma unroll
    for (int pass = 0; pass < 2; pass++) {
        const int le = pass * 32 + (tid >> 2);
        const int h  = tid & 3;
        const int dst = di_s[le];

        const float4* Kp = reinterpret_cast<const float4*>(kqv_s + le * KQV_STR +       h * 16);
        const float4* Qp = reinterpret_cast<const float4*>(kqv_s + le * KQV_STR +  64 + h * 16);
        const float4* Vp = reinterpret_cast<const float4*>(kqv_s + le * KQV_STR + 128 + h * 16);
        const float4* Ep = reinterpret_cast<const float4*>(E_s + le * EA_STR + h * 16);

        float p = 0.0f;
        #pragma unroll
        for (int q = 0; q < 4; q++) {
            float4 k = Kp[q];
            float4 qv = Qp[q];
            float4 e = Ep[q];
            p += k.x * qv.x * e.x + k.y * qv.y * e.y + k.z * qv.z * e.z + k.w * qv.w * e.w;
        }
        float s = __expf(fminf(fmaxf(p * 0.25f, -5.0f), 5.0f));

        float* ob = out + (size_t)dst * 64 + h * 16;
        #pragma unroll
        for (int q = 0; q < 4; q++) {
            float4 v = Vp[q];
            red_add_v4(ob + q * 4, v.x * s, v.y * s, v.z * s, v.w * s);
        }
        // Z: one red.v4 per edge (quad gather to h==0 lane)
        const int qbase = (tid & 31) & ~3;
        float s0 = __shfl_sync(0xffffffffu, s, qbase);
        float s1 = __shfl_sync(0xffffffffu, s, qbase + 1);
        float s2 = __shfl_sync(0xffffffffu, s, qbase + 2);
        float s3 = __shfl_sync(0xffffffffu, s, qbase + 3);
        if (h == 0)
            red_add_v4(g_Z + (size_t)dst * 4, s0, s1, s2, s3);
    }
}

// ---------------- finalize ----------------
__global__ void finalize_kernel(float* __restrict__ out) {
    int i = blockIdx.x * blockDim.x + threadIdx.x;
    if (i < N_NODES * HD) {
        int n = i >> 6;
        int h = (i >> 4) & 3;
        out[i] = out[i] / (g_Z[n * 4 + h] + 1e-6f);
    }
}

// ---------------- launch ----------------
extern "C" void kernel_launch(void* const* d_in, const int* in_sizes, int n_in,
                              void* d_out, int out_size) {
    const float* x   = (const float*)d_in[0];
    const float* ea  = (const float*)d_in[1];
    const int*   ei  = (const int*)  d_in[2];
    const float* WQ  = (const float*)d_in[3];
    const float* bQ  = (const float*)d_in[4];
    const float* WK  = (const float*)d_in[5];
    const float* bK  = (const float*)d_in[6];
    const float* WE  = (const float*)d_in[7];
    const float* bE  = (const float*)d_in[8];
    const float* WV  = (const float*)d_in[9];
    const float* bV  = (const float*)d_in[10];
    float* out = (float*)d_out;

    static_assert(EDGE_SMEM_FLOATS * 4 * 2 < 228 * 1024, "smem occupancy");
    cudaFuncSetAttribute(edge_kernel, cudaFuncAttributeMaxDynamicSharedMemorySize,
                         EDGE_SMEM_FLOATS * (int)sizeof(float));
    cudaFuncSetAttribute(proj_kernel, cudaFuncAttributeMaxDynamicSharedMemorySize,
                         PROJ_SMEM_FLOATS * (int)sizeof(float));

    zero_kernel<<<(N_NODES * HD + 255) / 256, 256>>>(out);
    {
        dim3 grid((N_NODES + 127) / 128, 3);
        proj_kernel<<<grid, 128, PROJ_SMEM_FLOATS * sizeof(float)>>>(x, WQ, bQ, WK, bK, WV, bV);
    }
    edge_kernel<<<N_EDGES / TILE_E, 128, EDGE_SMEM_FLOATS * sizeof(float)>>>(ea, ei, WE, bE, out);
    finalize_kernel<<<(N_NODES * HD + 255) / 256, 256>>>(out);
}

// round 17
// speedup vs baseline: 1.8051x; 1.8051x over previous
#include <cuda_runtime.h>
#include <cstdint>

#define N_NODES 50000
#define N_EDGES 1600000
#define IN_DIM 64
#define HD 64
#define NUM_HEADS 4
#define OUT_DIM 16

// ---------------- device scratch ----------------
__device__ float g_Q[N_NODES * HD];
__device__ float g_K[N_NODES * HD];
__device__ float g_V[N_NODES * HD];
__device__ float g_Z[N_NODES * NUM_HEADS];

// ---------------- helpers ----------------
__device__ __forceinline__ void red_add_v4(float* p, float a, float b, float c, float d) {
    asm volatile("red.global.add.v4.f32 [%0], {%1,%2,%3,%4};"
                 :: "l"(p), "f"(a), "f"(b), "f"(c), "f"(d) : "memory");
}
__device__ __forceinline__ uint32_t f2tf32(float f) {
    uint32_t r;
    asm("cvt.rna.tf32.f32 %0, %1;" : "=r"(r) : "f"(f));
    return r;
}
__device__ __forceinline__ void mma_tf32(float d[4], uint32_t a0, uint32_t a1,
                                         uint32_t a2, uint32_t a3,
                                         uint32_t b0, uint32_t b1) {
    asm("mma.sync.aligned.m16n8k8.row.col.f32.tf32.tf32.f32 "
        "{%0,%1,%2,%3}, {%4,%5,%6,%7}, {%8,%9}, {%0,%1,%2,%3};"
        : "+f"(d[0]), "+f"(d[1]), "+f"(d[2]), "+f"(d[3])
        : "r"(a0), "r"(a1), "r"(a2), "r"(a3), "r"(b0), "r"(b1));
}
// evict-last 32B load: keeps K/Q/V resident in L2 against the ea stream.
// (ptxas on sm_103 requires v8.b32 for L2::evict_last)
__device__ __forceinline__ void ldg_el8(const float* p, float4& v0, float4& v1) {
    asm("ld.global.nc.L2::evict_last.v8.b32 {%0,%1,%2,%3,%4,%5,%6,%7}, [%8];"
        : "=f"(v0.x), "=f"(v0.y), "=f"(v0.z), "=f"(v0.w),
          "=f"(v1.x), "=f"(v1.y), "=f"(v1.z), "=f"(v1.w)
        : "l"(p));
}

// ---------------- zero init (float4) ----------------
__global__ void zero_kernel(float4* __restrict__ out4) {
    int i = blockIdx.x * blockDim.x + threadIdx.x;
    if (i < N_NODES * HD / 4) out4[i] = make_float4(0.f, 0.f, 0.f, 0.f);
    if (i < N_NODES * NUM_HEADS / 4)
        reinterpret_cast<float4*>(g_Z)[i] = make_float4(0.f, 0.f, 0.f, 0.f);
}

// ---------------- node projections (R3 scalar, known good) ----------------
#define PROJ_SMEM_FLOATS (128 * 65 + 64 * 64 + 64)
__global__ __launch_bounds__(128)
void proj_kernel(const float* __restrict__ x,
                 const float* __restrict__ WQ, const float* __restrict__ bQ,
                 const float* __restrict__ WK, const float* __restrict__ bK,
                 const float* __restrict__ WV, const float* __restrict__ bV) {
    const float* W; const float* b; float* out;
    if (blockIdx.y == 0)      { W = WQ; b = bQ; out = g_Q; }
    else if (blockIdx.y == 1) { W = WK; b = bK; out = g_K; }
    else                      { W = WV; b = bV; out = g_V; }

    extern __shared__ float sm[];
    float* x_s = sm;
    float* w_s = sm + 128 * 65;
    float* b_s = w_s + 64 * 64;

    const int tid = threadIdx.x;
    const int base = blockIdx.x * 128;

    {
        const float4* W4 = reinterpret_cast<const float4*>(W);
        float4* ws4 = reinterpret_cast<float4*>(w_s);
        #pragma unroll
        for (int i = tid; i < 1024; i += 128) ws4[i] = W4[i];
    }
    if (tid < 64) b_s[tid] = b[tid];

    for (int f = tid; f < 128 * 16; f += 128) {
        int r = f >> 4, q = f & 15;
        int gr = base + r;
        if (gr >= N_NODES) gr = N_NODES - 1;
        float4 v = reinterpret_cast<const float4*>(x + (size_t)gr * 64)[q];
        float* d = x_s + r * 65 + q * 4;
        d[0] = v.x; d[1] = v.y; d[2] = v.z; d[3] = v.w;
    }
    __syncthreads();

    const int eg = tid >> 3, dg = tid & 7;

    float acc[8][8];
    #pragma unroll
    for (int i = 0; i < 8; i++)
        #pragma unroll
        for (int j = 0; j < 8; j++) acc[i][j] = 0.0f;

    const float4* ws4 = reinterpret_cast<const float4*>(w_s);
    #pragma unroll 4
    for (int c = 0; c < 64; c++) {
        float4 w0 = ws4[c * 16 + dg * 2];
        float4 w1 = ws4[c * 16 + dg * 2 + 1];
        float a[8];
        #pragma unroll
        for (int i = 0; i < 8; i++) a[i] = x_s[(eg * 8 + i) * 65 + c];
        #pragma unroll
        for (int i = 0; i < 8; i++) {
            acc[i][0] += a[i] * w0.x; acc[i][1] += a[i] * w0.y;
            acc[i][2] += a[i] * w0.z; acc[i][3] += a[i] * w0.w;
            acc[i][4] += a[i] * w1.x; acc[i][5] += a[i] * w1.y;
            acc[i][6] += a[i] * w1.z; acc[i][7] += a[i] * w1.w;
        }
    }

    float bb[8];
    #pragma unroll
    for (int j = 0; j < 8; j++) bb[j] = b_s[dg * 8 + j];
    #pragma unroll
    for (int i = 0; i < 8; i++) {
        int n = base + eg * 8 + i;
        if (n < N_NODES) {
            float4 o0 = make_float4(acc[i][0] + bb[0], acc[i][1] + bb[1], acc[i][2] + bb[2], acc[i][3] + bb[3]);
            float4 o1 = make_float4(acc[i][4] + bb[4], acc[i][5] + bb[5], acc[i][6] + bb[6], acc[i][7] + bb[7]);
            float4* dst = reinterpret_cast<float4*>(out + (size_t)n * 64 + dg * 8);
            dst[0] = o0; dst[1] = o1;
        }
    }
}

// ---------------- fused edge kernel: R14 structure + evict_last v8 K/Q/V ----
#define TILE_E   64
#define EA_OFF   0            // 64 rows x stride 68
#define EA_STR   68
#define W_OFF    (TILE_E * 68)   // 64 rows(k) x stride 72
#define W_STR    72
#define BIAS_OFF (W_OFF + 64 * 72)        // 64
#define SI_OFF   (BIAS_OFF + 64)          // 64 ints
#define DI_OFF   (SI_OFF + TILE_E)        // 64 ints
#define EDGE_SMEM_FLOATS (DI_OFF + TILE_E)

__global__ __launch_bounds__(128, 5)
void edge_kernel(const float* __restrict__ ea,
                 const int* __restrict__ eidx,
                 const float* __restrict__ WE, const float* __restrict__ bE,
                 float* __restrict__ out) {
    extern __shared__ float sm[];
    uint32_t* ea_s = reinterpret_cast<uint32_t*>(sm + EA_OFF);
    float* E_s     = sm + EA_OFF;               // reused after MMA
    uint32_t* w_s  = reinterpret_cast<uint32_t*>(sm + W_OFF);
    float* bias_s  = sm + BIAS_OFF;
    int* si_s      = reinterpret_cast<int*>(sm + SI_OFF);
    int* di_s      = reinterpret_cast<int*>(sm + DI_OFF);

    const int tid = threadIdx.x;
    const int base = blockIdx.x * TILE_E;

    if (tid < 64) bias_s[tid] = bE[tid];
    if (tid < TILE_E) {
        si_s[tid] = __ldcs(eidx + base + tid);              // streaming: don't pollute L2
        di_s[tid] = __ldcs(eidx + N_EDGES + base + tid);
    }

    // stage A = ea tile (tf32 bits), stride 68 — streaming loads (evict-first)
    for (int f = tid; f < TILE_E * 16; f += 128) {
        int r = f >> 4, q = f & 15;
        float4 v = __ldcs(reinterpret_cast<const float4*>(ea + (size_t)(base + r) * 64) + q);
        uint4 t;
        t.x = f2tf32(v.x); t.y = f2tf32(v.y); t.z = f2tf32(v.z); t.w = f2tf32(v.w);
        *reinterpret_cast<uint4*>(ea_s + r * EA_STR + q * 4) = t;
    }
    // stage B = WE (row-major [k][n]) as tf32 bits, stride 72
    for (int f = tid; f < 64 * 16; f += 128) {
        int k = f >> 4, q = f & 15;
        float4 v = reinterpret_cast<const float4*>(WE + (size_t)k * 64)[q];
        uint4 t;
        t.x = f2tf32(v.x); t.y = f2tf32(v.y); t.z = f2tf32(v.z); t.w = f2tf32(v.w);
        *reinterpret_cast<uint4*>(w_s + k * W_STR + q * 4) = t;
    }
    __syncthreads();

    const int lane = tid & 31;
    const int warp = tid >> 5;
    const int g  = lane >> 2;   // 0..7
    const int tg = lane & 3;    // 0..3
    const int wrow = warp * 16; // this warp's 16 edges

    // ---- Phase A: E = ea @ WE via m16n8k8 tf32 mma (one m-tile per warp) ----
    float acc[8][4];
    #pragma unroll
    for (int nt = 0; nt < 8; nt++)
        #pragma unroll
        for (int j = 0; j < 4; j++) acc[nt][j] = 0.0f;

    #pragma unroll
    for (int k8 = 0; k8 < 8; k8++) {
        const int r0 = wrow + g;
        uint32_t a0 = ea_s[(r0)     * EA_STR + k8 * 8 + tg];
        uint32_t a1 = ea_s[(r0 + 8) * EA_STR + k8 * 8 + tg];
        uint32_t a2 = ea_s[(r0)     * EA_STR + k8 * 8 + tg + 4];
        uint32_t a3 = ea_s[(r0 + 8) * EA_STR + k8 * 8 + tg + 4];
        #pragma unroll
        for (int nt = 0; nt < 8; nt++) {
            uint32_t b0 = w_s[(k8 * 8 + tg)     * W_STR + nt * 8 + g];
            uint32_t b1 = w_s[(k8 * 8 + tg + 4) * W_STR + nt * 8 + g];
            mma_tf32(acc[nt], a0, a1, a2, a3, b0, b1);
        }
    }

    // ---- store E (+bias) into this warp's own rows (no sync needed) ----
    #pragma unroll
    for (int rr = 0; rr < 2; rr++) {
        const int row = wrow + rr * 8 + g;
        #pragma unroll
        for (int nt = 0; nt < 8; nt++) {
            const int c0 = nt * 8 + tg * 2;
            float2 bb = *reinterpret_cast<const float2*>(bias_s + c0);
            *reinterpret_cast<float2*>(E_s + row * EA_STR + c0) =
                make_float2(acc[nt][rr * 2 + 0] + bb.x,
                            acc[nt][rr * 2 + 1] + bb.y);
        }
    }
    __syncthreads();

    // ---- Phase B: per (edge, head): score + scatter, evict_last v8 gathers ----
    #pragma unroll
    for (int pass = 0; pass < 2; pass++) {
        const int le = pass * 32 + (tid >> 2);
        const int h  = tid & 3;
        const int src = si_s[le];
        const int dst = di_s[le];

        const float* Kb = g_K + (size_t)src * 64 + h * 16;
        const float* Qb = g_Q + (size_t)dst * 64 + h * 16;
        const float4* Ep = reinterpret_cast<const float4*>(E_s + le * EA_STR + h * 16);

        float4 k0, k1, k2, k3, q0, q1, q2, q3;
        ldg_el8(Kb,     k0, k1);
        ldg_el8(Kb + 8, k2, k3);
        ldg_el8(Qb,     q0, q1);
        ldg_el8(Qb + 8, q2, q3);

        float4 e0 = Ep[0], e1 = Ep[1], e2 = Ep[2], e3 = Ep[3];
        float p =
            k0.x * q0.x * e0.x + k0.y * q0.y * e0.y + k0.z * q0.z * e0.z + k0.w * q0.w * e0.w +
            k1.x * q1.x * e1.x + k1.y * q1.y * e1.y + k1.z * q1.z * e1.z + k1.w * q1.w * e1.w +
            k2.x * q2.x * e2.x + k2.y * q2.y * e2.y + k2.z * q2.z * e2.z + k2.w * q2.w * e2.w +
            k3.x * q3.x * e3.x + k3.y * q3.y * e3.y + k3.z * q3.z * e3.z + k3.w * q3.w * e3.w;

        float s = __expf(fminf(fmaxf(p * 0.25f, -5.0f), 5.0f));

        const float* Vb = g_V + (size_t)src * 64 + h * 16;
        float4 v0, v1, v2, v3;
        ldg_el8(Vb,     v0, v1);
        ldg_el8(Vb + 8, v2, v3);

        float* ob = out + (size_t)dst * 64 + h * 16;
        red_add_v4(ob,      v0.x * s, v0.y * s, v0.z * s, v0.w * s);
        red_add_v4(ob + 4,  v1.x * s, v1.y * s, v1.z * s, v1.w * s);
        red_add_v4(ob + 8,  v2.x * s, v2.y * s, v2.z * s, v2.w * s);
        red_add_v4(ob + 12, v3.x * s, v3.y * s, v3.z * s, v3.w * s);

        // Z: one red.v4 per edge (gather the quad's 4 head scores to h==0 lane)
        const int qbase = (tid & 31) & ~3;
        float s0 = __shfl_sync(0xffffffffu, s, qbase);
        float s1 = __shfl_sync(0xffffffffu, s, qbase + 1);
        float s2 = __shfl_sync(0xffffffffu, s, qbase + 2);
        float s3 = __shfl_sync(0xffffffffu, s, qbase + 3);
        if (h == 0)
            red_add_v4(g_Z + (size_t)dst * 4, s0, s1, s2, s3);
    }
}

// ---------------- finalize (float4) ----------------
__global__ void finalize_kernel(float4* __restrict__ out4) {
    int i = blockIdx.x * blockDim.x + threadIdx.x;
    if (i < N_NODES * HD / 4) {
        int n = i >> 4;            // 16 float4 per node
        int h = (i >> 2) & 3;      // 4 float4 per head
        float inv = 1.0f / (g_Z[n * 4 + h] + 1e-6f);
        float4 v = out4[i];
        out4[i] = make_float4(v.x * inv, v.y * inv, v.z * inv, v.w * inv);
    }
}

// ---------------- launch ----------------
extern "C" void kernel_launch(void* const* d_in, const int* in_sizes, int n_in,
                              void* d_out, int out_size) {
    const float* x   = (const float*)d_in[0];
    const float* ea  = (const float*)d_in[1];
    const int*   ei  = (const int*)  d_in[2];
    const float* WQ  = (const float*)d_in[3];
    const float* bQ  = (const float*)d_in[4];
    const float* WK  = (const float*)d_in[5];
    const float* bK  = (const float*)d_in[6];
    const float* WE  = (const float*)d_in[7];
    const float* bE  = (const float*)d_in[8];
    const float* WV  = (const float*)d_in[9];
    const float* bV  = (const float*)d_in[10];
    float* out = (float*)d_out;

    static_assert(EDGE_SMEM_FLOATS * 4 * 5 < 228 * 1024, "smem occupancy");
    cudaFuncSetAttribute(edge_kernel, cudaFuncAttributeMaxDynamicSharedMemorySize,
                         EDGE_SMEM_FLOATS * (int)sizeof(float));
    cudaFuncSetAttribute(proj_kernel, cudaFuncAttributeMaxDynamicSharedMemorySize,
                         PROJ_SMEM_FLOATS * (int)sizeof(float));

    zero_kernel<<<(N_NODES * HD / 4 + 255) / 256, 256>>>((float4*)out);
    {
        dim3 grid((N_NODES + 127) / 128, 3);
        proj_kernel<<<grid, 128, PROJ_SMEM_FLOATS * sizeof(float)>>>(x, WQ, bQ, WK, bK, WV, bV);
    }
    edge_kernel<<<N_EDGES / TILE_E, 128, EDGE_SMEM_FLOATS * sizeof(float)>>>(ea, ei, WE, bE, out);
    finalize_kernel<<<(N_NODES * HD / 4 + 255) / 256, 256>>>((float4*)out);
}